// round 16
// baseline (speedup 1.0000x reference)
#include <cuda_runtime.h>
#include <cstdint>

#define TABLE_N   262144
#define CLUSTER   16
#define SHARD     (TABLE_N / CLUSTER)   // 16384 entries per CTA (128 KB)
#define TPB       512
#define PPT       8
#define TILE      (TPB * PPT)           // 4096 points per tile
#define GRID_CTAS 128                   // 8 clusters of 16
#define SMEM_BYTES (SHARD * 8)          // 131072

__device__ __forceinline__ unsigned part1by1(unsigned x) {
    x &= 0x0000ffffu;
    x = (x | (x << 8)) & 0x00FF00FFu;
    x = (x | (x << 4)) & 0x0F0F0F0Fu;
    x = (x | (x << 2)) & 0x33333333u;
    x = (x | (x << 1)) & 0x55555555u;
    return x;
}

// XLA-lowered index path: divide-by-constant == multiply by f32 reciprocal.
__device__ __forceinline__ int quad_index(float px, float py) {
    const float SCALE   = 10000000.0f;
    const float R_SCALE = 1.0f / 10000000.0f;
    const float R_W     = 1.0f / 360.0f;
    const float R_H     = 1.0f / 180.0f;
    float cx = __fmul_rn(rintf(__fmul_rn(px, SCALE)), R_SCALE);
    float cy = __fmul_rn(rintf(__fmul_rn(py, SCALE)), R_SCALE);
    float u  = __fmul_rn(__fadd_rn(cx, 180.0f), R_W);
    float v  = __fmul_rn(__fadd_rn(cy,  90.0f), R_H);
    int ix = (int)__fmul_rn(u, 512.0f);
    int iy = (int)__fmul_rn(v, 512.0f);
    ix = min(max(ix, 0), 511);
    iy = min(max(iy, 0), 511);
    return (int)(part1by1((unsigned)ix) | (part1by1((unsigned)iy) << 1));
}

// Cluster kernel: each CTA owns a 16384-entry interleaved (w,b) shard in its
// SMEM; gathers route via DSMEM (mapa + ld.shared::cluster) to the owning
// rank, bypassing the L1tex global-wavefront pipe that capped all previous
// kernels at ~41us.
__global__ void __launch_bounds__(TPB)
quadpool_cluster_kernel(const float2* __restrict__ in2,  // [n]
                        const float*  __restrict__ x,    // [n]
                        const float4* __restrict__ w4,   // [TABLE_N/4]
                        const float4* __restrict__ b4,   // [TABLE_N/4]
                        float*        __restrict__ out,  // [n]
                        int ntiles)
{
    extern __shared__ __align__(16) float2 s_wb[];       // [SHARD]

    const int tid = threadIdx.x;
    uint32_t rank;
    asm("mov.u32 %0, %%cluster_ctarank;" : "=r"(rank));

    // --- Fill this CTA's shard: table entries [rank*SHARD, (rank+1)*SHARD).
    {
        const float4* ws = w4 + rank * (SHARD / 4);
        const float4* bs = b4 + rank * (SHARD / 4);
#pragma unroll
        for (int j = tid; j < SHARD / 4; j += TPB) {     // 8 iterations
            float4 w = ws[j];
            float4 b = bs[j];
            s_wb[4 * j + 0] = make_float2(w.x, b.x);
            s_wb[4 * j + 1] = make_float2(w.y, b.y);
            s_wb[4 * j + 2] = make_float2(w.z, b.z);
            s_wb[4 * j + 3] = make_float2(w.w, b.w);
        }
    }
    asm volatile("barrier.cluster.arrive.aligned;" ::: "memory");
    asm volatile("barrier.cluster.wait.aligned;" ::: "memory");

    uint32_t sbase;
    asm("{ .reg .u64 t; cvta.to.shared.u64 t, %1; cvt.u32.u64 %0, t; }"
        : "=r"(sbase) : "l"(s_wb));

    // --- Persistent loop over 4096-point tiles.
    for (int t = blockIdx.x; t < ntiles; t += gridDim.x) {
        const int base = t * TILE + tid;

        float2 p[PPT];
#pragma unroll
        for (int j = 0; j < PPT; j++)
            p[j] = __ldcs(&in2[base + j * TPB]);

        int idx[PPT];
#pragma unroll
        for (int j = 0; j < PPT; j++)
            idx[j] = quad_index(p[j].x, p[j].y);

        // DSMEM gathers: rank = idx>>14, offset = (idx & 16383)*8 bytes.
        float wv[PPT], bv[PPT];
#pragma unroll
        for (int j = 0; j < PPT; j++) {
            uint32_t trank = ((unsigned)idx[j]) >> 14;
            uint32_t saddr = sbase + (((unsigned)idx[j]) & 0x3FFFu) * 8u;
            uint32_t raddr;
            asm("mapa.shared::cluster.u32 %0, %1, %2;"
                : "=r"(raddr) : "r"(saddr), "r"(trank));
            asm volatile("ld.shared::cluster.v2.f32 {%0, %1}, [%2];"
                         : "=f"(wv[j]), "=f"(bv[j]) : "r"(raddr));
        }

        float xv[PPT];
#pragma unroll
        for (int j = 0; j < PPT; j++)
            xv[j] = __ldcs(&x[base + j * TPB]);

#pragma unroll
        for (int j = 0; j < PPT; j++)
            __stcs(&out[base + j * TPB], fmaf(wv[j], xv[j], bv[j]));
    }

    // No CTA may exit while peers can still read its shard.
    asm volatile("barrier.cluster.arrive.aligned;" ::: "memory");
    asm volatile("barrier.cluster.wait.aligned;" ::: "memory");
}

// Tail: direct two-gather path (no table), for n % 4096 points only.
__global__ void quadpool_tail_kernel(const float2* __restrict__ in2,
                                     const float*  __restrict__ x,
                                     const float*  __restrict__ w,
                                     const float*  __restrict__ b,
                                     float* __restrict__ out,
                                     int start, int n)
{
    int i = start + blockIdx.x * blockDim.x + threadIdx.x;
    if (i >= n) return;
    float2 pt = in2[i];
    int idx = quad_index(pt.x, pt.y);
    out[i] = fmaf(__ldg(&w[idx]), x[i], __ldg(&b[idx]));
}

extern "C" void kernel_launch(void* const* d_in, const int* in_sizes, int n_in,
                              void* d_out, int out_size)
{
    const float* in  = (const float*)d_in[0];   // [N,2]
    const float* x   = (const float*)d_in[1];   // [N]
    const float* w   = (const float*)d_in[2];   // [262144]
    const float* b   = (const float*)d_in[3];   // [262144]
    float* out = (float*)d_out;

    int n = in_sizes[1];
    int ntiles = n / TILE;

    if (ntiles > 0) {
        // Idempotent attribute setup (no static guards; cheap).
        cudaFuncSetAttribute(quadpool_cluster_kernel,
                             cudaFuncAttributeNonPortableClusterSizeAllowed, 1);
        cudaFuncSetAttribute(quadpool_cluster_kernel,
                             cudaFuncAttributeMaxDynamicSharedMemorySize,
                             SMEM_BYTES);

        cudaLaunchConfig_t cfg = {};
        int grid = GRID_CTAS;
        cfg.gridDim  = dim3((unsigned)grid, 1, 1);
        cfg.blockDim = dim3(TPB, 1, 1);
        cfg.dynamicSmemBytes = SMEM_BYTES;
        cfg.stream = 0;
        cudaLaunchAttribute attrs[1];
        attrs[0].id = cudaLaunchAttributeClusterDimension;
        attrs[0].val.clusterDim.x = CLUSTER;
        attrs[0].val.clusterDim.y = 1;
        attrs[0].val.clusterDim.z = 1;
        cfg.attrs = attrs;
        cfg.numAttrs = 1;

        cudaLaunchKernelEx(&cfg, quadpool_cluster_kernel,
                           (const float2*)in, x,
                           (const float4*)w, (const float4*)b,
                           out, ntiles);
    }

    int done = ntiles * TILE;
    int rem = n - done;
    if (rem > 0) {
        quadpool_tail_kernel<<<(rem + 255) / 256, 256>>>(
            (const float2*)in, x, w, b, out, done, n);
    }
}